// round 4
// baseline (speedup 1.0000x reference)
#include <cuda_runtime.h>

#define G        64
#define IMGSZ    512
#define NTHREADS 256

__device__ __forceinline__ float ldimg(const float* __restrict__ img, int gy, int gx) {
    if ((unsigned)gy < IMGSZ && (unsigned)gx < IMGSZ)
        return __ldg(img + gy * IMGSZ + gx);
    return 0.0f;
}

// ---------------- S = 4 ----------------
// Weights: [1,3,5,7,7,5,3,1]/32
template <int ROWS>
__device__ void ds4_slice(const float* __restrict__ img, float* __restrict__ o,
                          int by, int bx, int y0, float* __restrict__ tmp) {
    constexpr int PS = 256, LR = 4 * ROWS + 4;
    constexpr float W0=1.f/32, W1=3.f/32, W2=5.f/32, W3=7.f/32,
                    W4=7.f/32, W5=5.f/32, W6=3.f/32, W7=1.f/32;
    const float W[8] = {W0,W1,W2,W3,W4,W5,W6,W7};
    const int tid = threadIdx.x;
    const int rb  = 4 * y0 - 2;

    // ---- phase 1: horizontal, tmp[LR][64] ----
    for (int idx = tid; idx < LR * G; idx += NTHREADS) {
        int lr = idx >> 6;
        int r  = rb + lr;
        if ((unsigned)r >= (unsigned)PS) continue;   // never read by phase 2
        int i  = idx & 63;
        int gy = by + r;
        int j0 = 4 * i - 2;
        bool row_ok = (unsigned)gy < IMGSZ;

        if (i >= 1 && i <= 62) {                     // interior column, wsum==1
            if (!row_ok) { tmp[idx] = 0.0f; continue; }
            int gx0 = bx + j0;
            const float* rowp = img + gy * IMGSZ;
            float acc;
            if (gx0 >= 0 && gx0 + 8 <= IMGSZ) {
                int base = gx0 & ~3;                 // base <= 500 always -> safe
                int off  = gx0 & 3;                  // warp-uniform
                const float4* p = (const float4*)(rowp + base);
                if (off == 0) {
                    float4 a = __ldg(p);
                    acc = W0*a.x + W1*a.y + W2*a.z + W3*a.w;
                    float4 b = __ldg(p + 1);
                    acc += W4*b.x + W5*b.y + W6*b.z + W7*b.w;
                } else if (off == 1) {
                    float4 a = __ldg(p);
                    acc = W0*a.y + W1*a.z + W2*a.w;
                    float4 b = __ldg(p + 1);
                    acc += W3*b.x + W4*b.y + W5*b.z + W6*b.w;
                    float4 c = __ldg(p + 2);
                    acc += W7*c.x;
                } else if (off == 2) {
                    float4 a = __ldg(p);
                    acc = W0*a.z + W1*a.w;
                    float4 b = __ldg(p + 1);
                    acc += W2*b.x + W3*b.y + W4*b.z + W5*b.w;
                    float4 c = __ldg(p + 2);
                    acc += W6*c.x + W7*c.y;
                } else {
                    float4 a = __ldg(p);
                    acc = W0*a.w;
                    float4 b = __ldg(p + 1);
                    acc += W1*b.x + W2*b.y + W3*b.z + W4*b.w;
                    float4 c = __ldg(p + 2);
                    acc += W5*c.x + W6*c.y + W7*c.z;
                }
            } else {                                 // image-clipped: zero-pad, full weight
                acc = 0.0f;
#pragma unroll
                for (int k = 0; k < 8; k++) {
                    int gx = gx0 + k;
                    if ((unsigned)gx < IMGSZ) acc += W[k] * __ldg(rowp + gx);
                }
            }
            tmp[idx] = acc;
        } else {                                     // patch-edge column: renormalize
            float acc = 0.0f, wsum = 0.0f;
            const float* rowp = img + gy * IMGSZ;
#pragma unroll
            for (int k = 0; k < 8; k++) {
                int j = j0 + k;
                if ((unsigned)j < (unsigned)PS) {
                    int gx = bx + j;
                    if (row_ok && (unsigned)gx < IMGSZ) acc += W[k] * __ldg(rowp + gx);
                    wsum += W[k];
                }
            }
            tmp[idx] = acc / wsum;
        }
    }
    __syncthreads();

    // ---- phase 2: vertical ----
    for (int idx = tid; idx < ROWS * G; idx += NTHREADS) {
        int y  = y0 + (idx >> 6);
        int x  = idx & 63;
        int r0 = 4 * y - 2;
        float acc;
        if (r0 >= 0 && r0 + 8 <= PS) {
            const float* t = tmp + (r0 - rb) * G + x;
            acc = W0*t[0*G] + W1*t[1*G] + W2*t[2*G] + W3*t[3*G]
                + W4*t[4*G] + W5*t[5*G] + W6*t[6*G] + W7*t[7*G];
        } else {
            acc = 0.0f; float wsum = 0.0f;
#pragma unroll
            for (int k = 0; k < 8; k++) {
                int r = r0 + k;
                if ((unsigned)r < (unsigned)PS) {
                    acc  += W[k] * tmp[(r - rb) * G + x];
                    wsum += W[k];
                }
            }
            acc /= wsum;
        }
        o[y * G + x] = acc;
    }
}

// ---------------- S = 2 ----------------
// Weights: [1,3,3,1]/8. Phase 1 pairs two adjacent outputs per thread so the
// lane stride is 4 floats (uniform alignment) and loads vectorize.
template <int ROWS>
__device__ void ds2_slice(const float* __restrict__ img, float* __restrict__ o,
                          int by, int bx, int y0, float* __restrict__ tmp) {
    constexpr int PS = 128, LR = 2 * ROWS + 2;
    constexpr float W0=0.125f, W1=0.375f, W2=0.375f, W3=0.125f;
    const float W[4] = {W0,W1,W2,W3};
    const int tid = threadIdx.x;
    const int rb  = 2 * y0 - 1;

    // ---- phase 1: horizontal, 32 threads/row, 2 outputs/thread ----
    for (int idx = tid; idx < LR * 32; idx += NTHREADS) {
        int lr = idx >> 5;
        int r  = rb + lr;
        if ((unsigned)r >= (unsigned)PS) continue;
        int t  = idx & 31;
        int gy = by + r;
        bool row_ok = (unsigned)gy < IMGSZ;
        int j0 = 4 * t - 1;                 // union span [j0, j0+6)
        float a0, a1;

        if (t >= 1 && t <= 30) {            // both outputs interior, wsum==1
            if (!row_ok) { a0 = 0.0f; a1 = 0.0f; }
            else {
                int gx0 = bx + j0;
                const float* rowp = img + gy * IMGSZ;
                if (gx0 >= 0 && gx0 + 6 <= IMGSZ) {
                    int base = gx0 & ~3;    // safe: worst read base+12 <= 512
                    int off  = gx0 & 3;
                    const float4* p = (const float4*)(rowp + base);
                    float4 a = __ldg(p), b = __ldg(p + 1);
                    if (off == 0) {
                        a0 = W0*a.x + W1*a.y + W2*a.z + W3*a.w;
                        a1 = W0*a.z + W1*a.w + W2*b.x + W3*b.y;
                    } else if (off == 1) {
                        a0 = W0*a.y + W1*a.z + W2*a.w + W3*b.x;
                        a1 = W0*a.w + W1*b.x + W2*b.y + W3*b.z;
                    } else if (off == 2) {
                        a0 = W0*a.z + W1*a.w + W2*b.x + W3*b.y;
                        a1 = W0*b.x + W1*b.y + W2*b.z + W3*b.w;
                    } else {
                        float4 c = __ldg(p + 2);
                        a0 = W0*a.w + W1*b.x + W2*b.y + W3*b.z;
                        a1 = W0*b.y + W1*b.z + W2*b.w + W3*c.x;
                    }
                } else {                     // image-clipped: per-tap zero pad
                    float v[6];
#pragma unroll
                    for (int k = 0; k < 6; k++) {
                        int gx = gx0 + k;
                        v[k] = ((unsigned)gx < IMGSZ) ? __ldg(rowp + gx) : 0.0f;
                    }
                    a0 = W0*v[0] + W1*v[1] + W2*v[2] + W3*v[3];
                    a1 = W0*v[2] + W1*v[3] + W2*v[4] + W3*v[5];
                }
            }
        } else {                             // t==0 or t==31: general renorm per output
            const float* rowp = img + gy * IMGSZ;
#pragma unroll
            for (int u = 0; u < 2; u++) {
                int jj0 = 2 * (2 * t + u) - 1;
                float acc = 0.0f, wsum = 0.0f;
#pragma unroll
                for (int k = 0; k < 4; k++) {
                    int j = jj0 + k;
                    if ((unsigned)j < (unsigned)PS) {
                        int gx = bx + j;
                        if (row_ok && (unsigned)gx < IMGSZ) acc += W[k] * __ldg(rowp + gx);
                        wsum += W[k];
                    }
                }
                if (u == 0) a0 = acc / wsum; else a1 = acc / wsum;
            }
        }
        ((float2*)(tmp + lr * G))[t] = make_float2(a0, a1);
    }
    __syncthreads();

    // ---- phase 2: vertical ----
    for (int idx = tid; idx < ROWS * G; idx += NTHREADS) {
        int y  = y0 + (idx >> 6);
        int x  = idx & 63;
        int r0 = 2 * y - 1;
        float acc;
        if (r0 >= 0 && r0 + 4 <= PS) {
            const float* t = tmp + (r0 - rb) * G + x;
            acc = W0*t[0*G] + W1*t[1*G] + W2*t[2*G] + W3*t[3*G];
        } else {
            acc = 0.0f; float wsum = 0.0f;
#pragma unroll
            for (int k = 0; k < 4; k++) {
                int r = r0 + k;
                if ((unsigned)r < (unsigned)PS) {
                    acc  += W[k] * tmp[(r - rb) * G + x];
                    wsum += W[k];
                }
            }
            acc /= wsum;
        }
        o[y * G + x] = acc;
    }
}

// Grid (1344 blocks), heavy work first:
//   [0, 768)     : S=4, 4 slices x 16 rows per (b,c)
//   [768, 1152)  : S=2, 2 slices x 32 rows per (b,c)
//   [1152, 1344) : direct 64x64 zero-padded crop of img0
__global__ __launch_bounds__(NTHREADS, 8)
void glimpse_kernel(const float* __restrict__ img0,
                    const float* __restrict__ img2,
                    const float* __restrict__ img4,
                    const float* __restrict__ loc,
                    float* __restrict__ out) {
    extern __shared__ float tmp[];

    int blk = blockIdx.x;
    int sel, bc, slice;
    if (blk < 768)       { sel = 0; bc = blk >> 2;          slice = blk & 3; }
    else if (blk < 1152) { sel = 1; bc = (blk - 768) >> 1;  slice = (blk - 768) & 1; }
    else                 { sel = 2; bc = blk - 1152;        slice = 0; }
    int b = bc / 3;
    int c = bc - b * 3;

    float lx = loc[2 * b + 0];
    float ly = loc[2 * b + 1];
    int sx = (int)(0.5f * ((lx + 1.0f) * 511.0f));
    int sy = (int)(0.5f * ((ly + 1.0f) * 511.0f));

    if (sel == 0) {
        const float* img = img4 + (size_t)(b * 3 + c) * IMGSZ * IMGSZ;
        float* o = out + (size_t)((b * 3 + 2) * 3 + c) * G * G;
        ds4_slice<16>(img, o, sy - 128, sx - 128, slice * 16, tmp);
    } else if (sel == 1) {
        const float* img = img2 + (size_t)(b * 3 + c) * IMGSZ * IMGSZ;
        float* o = out + (size_t)((b * 3 + 1) * 3 + c) * G * G;
        ds2_slice<32>(img, o, sy - 64, sx - 64, slice * 32, tmp);
    } else {
        const float* img = img0 + (size_t)(b * 3 + c) * IMGSZ * IMGSZ;
        float* o = out + (size_t)((b * 3 + 0) * 3 + c) * G * G;
        int by = sy - G / 2, bx = sx - G / 2;
        for (int idx = threadIdx.x; idx < G * G; idx += NTHREADS) {
            int y = idx >> 6, x = idx & 63;
            o[idx] = ldimg(img, by + y, bx + x);
        }
    }
}

extern "C" void kernel_launch(void* const* d_in, const int* in_sizes, int n_in,
                              void* d_out, int out_size) {
    const float* img0 = (const float*)d_in[0];
    const float* img2 = (const float*)d_in[1];
    const float* img4 = (const float*)d_in[2];
    const float* loc  = (const float*)d_in[3];
    float* out = (float*)d_out;

    const size_t smem = (size_t)68 * G * sizeof(float);  // 17408 B
    cudaFuncSetAttribute(glimpse_kernel,
                         cudaFuncAttributeMaxDynamicSharedMemorySize, (int)smem);
    glimpse_kernel<<<1344, NTHREADS, smem>>>(img0, img2, img4, loc, out);
}